// round 3
// baseline (speedup 1.0000x reference)
#include <cuda_runtime.h>

// Warp1DOp: out[n,c,h,w] = bilinear 1-D sample of img[n,c,h,:] at x = w - disp[n,0,h,w]
// with zeros padding semantics matching torch grid_sample-style reference:
//   xc = clip(w - disp, -1, W) + 1  in [0, W+1]; padded cols 0 and W+1 are zero.
//
// One thread per (n,h,w); coordinate math computed once, reused across C=32 channels.
// Stores coalesced per channel iteration; gather loads are local (|disp| ~ 20-60)
// so L1/L2 absorb the scatter and DRAM sees ~one pass over img.

#define N_ 4
#define C_ 32
#define H_ 384
#define W_ 1280
#define HW_ (H_ * W_)
#define CHW_ (C_ * HW_)
#define NHW_ (N_ * H_ * W_)

__global__ __launch_bounds__(256) void warp1d_kernel(
    const float* __restrict__ img,
    const float* __restrict__ disp,
    float* __restrict__ out)
{
    int idx = blockIdx.x * blockDim.x + threadIdx.x;  // over N*H*W
    if (idx >= NHW_) return;

    int w  = idx % W_;
    int nh = idx / W_;          // n*H + h
    int n  = nh / H_;
    int h  = nh % H_;

    float d = disp[idx];
    float x = (float)w - d;
    x = fminf(fmaxf(x, -1.0f), (float)W_) + 1.0f;   // [0, W+1], padded coords
    float xf = floorf(x);
    int   x0 = (int)xf;
    float dx = x - xf;
    int   x1 = x0 + (dx > 0.0f ? 1 : 0);            // == ceil(x)

    // padded index p holds real data for p in [1, W] -> img column p-1
    int  c0 = x0 - 1;
    int  c1 = x1 - 1;
    bool v0 = ((unsigned)c0 < (unsigned)W_);
    bool v1 = ((unsigned)c1 < (unsigned)W_);
    float one_m_dx = 1.0f - dx;

    size_t base = (size_t)n * CHW_ + (size_t)h * W_;   // c = 0 row offset
    const float* __restrict__ irow = img + base;
    float* __restrict__ orow = out + base + w;

#pragma unroll 8
    for (int c = 0; c < C_; ++c) {
        const float* r = irow + (size_t)c * HW_;
        float a = v0 ? __ldg(r + c0) : 0.0f;
        float b = v1 ? __ldg(r + c1) : 0.0f;
        orow[(size_t)c * HW_] = one_m_dx * a + dx * b;
    }
}

extern "C" void kernel_launch(void* const* d_in, const int* in_sizes, int n_in,
                              void* d_out, int out_size)
{
    const float* img  = (const float*)d_in[0];
    const float* disp = (const float*)d_in[1];
    float* out = (float*)d_out;

    const int threads = 256;
    const int blocks  = (NHW_ + threads - 1) / threads;
    warp1d_kernel<<<blocks, threads>>>(img, disp, out);
}

// round 4
// speedup vs baseline: 1.0200x; 1.0200x over previous
#include <cuda_runtime.h>

// Warp1DOp, 4 pixels per thread (float4 disp load + float4 store).
// out[n,c,h,w] = (1-dx)*imgp[x0] + dx*imgp[x1], x = clip(w - disp, -1, W) + 1,
// zeros padding (padded cols 0 and W+1).
//
// Coordinate math computed once per (n,h,w), reused across C=32 channels.
// 8 independent gather LDGs per channel iteration per thread -> high MLP;
// STG.128 coalesced stores; LDG.128 disp read.

#define N_ 4
#define C_ 32
#define H_ 384
#define W_ 1280
#define HW_ (H_ * W_)
#define CHW_ (C_ * HW_)
#define NHW_ (N_ * H_ * W_)
#define W4_ (W_ / 4)
#define NHW4_ (NHW_ / 4)

__global__ __launch_bounds__(256) void warp1d_kernel(
    const float* __restrict__ img,
    const float* __restrict__ disp,
    float* __restrict__ out)
{
    int t = blockIdx.x * blockDim.x + threadIdx.x;   // over N*H*W/4
    if (t >= NHW4_) return;

    int w4 = t % W4_;
    int nh = t / W4_;           // n*H + h
    int n  = nh / H_;
    int h  = nh % H_;
    int w  = w4 * 4;

    float4 d4 = reinterpret_cast<const float4*>(disp)[t];
    float dv[4] = {d4.x, d4.y, d4.z, d4.w};

    int   c0[4], c1[4];
    float dx[4], mdx[4];
    bool  v0[4], v1[4];

#pragma unroll
    for (int i = 0; i < 4; ++i) {
        float x = (float)(w + i) - dv[i];
        x = fminf(fmaxf(x, -1.0f), (float)W_) + 1.0f;   // [0, W+1] padded coord
        float xf = floorf(x);
        int   p0 = (int)xf;
        float f  = x - xf;
        int   p1 = p0 + (f > 0.0f ? 1 : 0);             // == ceil(x)
        c0[i] = p0 - 1;                                  // real img column
        c1[i] = p1 - 1;
        v0[i] = ((unsigned)c0[i] < (unsigned)W_);
        v1[i] = ((unsigned)c1[i] < (unsigned)W_);
        dx[i]  = f;
        mdx[i] = 1.0f - f;
    }

    size_t base = (size_t)n * CHW_ + (size_t)h * W_;
    const float* __restrict__ irow = img + base;
    float* __restrict__ orow = out + base + w;

#pragma unroll 4
    for (int c = 0; c < C_; ++c) {
        const float* r = irow + (size_t)c * HW_;
        float a0 = v0[0] ? __ldg(r + c0[0]) : 0.0f;
        float b0 = v1[0] ? __ldg(r + c1[0]) : 0.0f;
        float a1 = v0[1] ? __ldg(r + c0[1]) : 0.0f;
        float b1 = v1[1] ? __ldg(r + c1[1]) : 0.0f;
        float a2 = v0[2] ? __ldg(r + c0[2]) : 0.0f;
        float b2 = v1[2] ? __ldg(r + c1[2]) : 0.0f;
        float a3 = v0[3] ? __ldg(r + c0[3]) : 0.0f;
        float b3 = v1[3] ? __ldg(r + c1[3]) : 0.0f;

        float4 o;
        o.x = mdx[0] * a0 + dx[0] * b0;
        o.y = mdx[1] * a1 + dx[1] * b1;
        o.z = mdx[2] * a2 + dx[2] * b2;
        o.w = mdx[3] * a3 + dx[3] * b3;
        *reinterpret_cast<float4*>(orow + (size_t)c * HW_) = o;
    }
}

extern "C" void kernel_launch(void* const* d_in, const int* in_sizes, int n_in,
                              void* d_out, int out_size)
{
    const float* img  = (const float*)d_in[0];
    const float* disp = (const float*)d_in[1];
    float* out = (float*)d_out;

    const int threads = 256;
    const int blocks  = (NHW4_ + threads - 1) / threads;
    warp1d_kernel<<<blocks, threads>>>(img, disp, out);
}